// round 15
// baseline (speedup 1.0000x reference)
#include <cuda_runtime.h>
#include <cuda_fp16.h>
#include <math.h>
#include <stdint.h>

// Problem constants
#define B_   2
#define T_   2048
#define C_   1024
#define H_   16
#define M_   (B_ * T_)      // 4096
#define N3C_ (3 * C_)       // 3072
#define KD1_ 1024           // single-fp16 K width

// ---------------------------------------------------------------------------
// Helpers
// ---------------------------------------------------------------------------
__device__ __forceinline__ uint32_t smem_u32(const void* p) {
    uint32_t a;
    asm("{ .reg .u64 t; cvta.to.shared.u64 t, %1; cvt.u32.u64 %0, t; }"
        : "=r"(a) : "l"(p));
    return a;
}

__device__ __forceinline__ void ldsm_x4(uint32_t (&r)[4], uint32_t addr) {
    asm volatile("ldmatrix.sync.aligned.m8n8.x4.shared.b16 {%0,%1,%2,%3}, [%4];"
                 : "=r"(r[0]), "=r"(r[1]), "=r"(r[2]), "=r"(r[3]) : "r"(addr));
}

__device__ __forceinline__ void ldsm_x4_t(uint32_t (&r)[4], uint32_t addr) {
    asm volatile("ldmatrix.sync.aligned.m8n8.x4.trans.shared.b16 {%0,%1,%2,%3}, [%4];"
                 : "=r"(r[0]), "=r"(r[1]), "=r"(r[2]), "=r"(r[3]) : "r"(addr));
}

__device__ __forceinline__ void mma_f16(float (&c)[4], const uint32_t (&a)[4],
                                        uint32_t b0, uint32_t b1) {
    asm volatile(
        "mma.sync.aligned.m16n8k16.row.col.f32.f16.f16.f32 "
        "{%0,%1,%2,%3}, {%4,%5,%6,%7}, {%8,%9}, {%0,%1,%2,%3};"
        : "+f"(c[0]), "+f"(c[1]), "+f"(c[2]), "+f"(c[3])
        : "r"(a[0]), "r"(a[1]), "r"(a[2]), "r"(a[3]), "r"(b0), "r"(b1));
}

// pack two f32 -> f16x2, first arg in lower half
__device__ __forceinline__ uint32_t packh(float lo, float hi) {
    uint32_t u;
    asm("cvt.rn.f16x2.f32 %0, %1, %2;" : "=r"(u) : "f"(hi), "f"(lo));
    return u;
}

__device__ __forceinline__ void cp16(uint32_t dst, const void* src) {
    asm volatile("cp.async.cg.shared.global [%0], [%1], 16;"
                 :: "r"(dst), "l"(src) : "memory");
}
#define CP_COMMIT() asm volatile("cp.async.commit_group;" ::: "memory")
#define CP_WAIT1()  asm volatile("cp.async.wait_group 1;" ::: "memory")
#define CP_WAIT0()  asm volatile("cp.async.wait_group 0;" ::: "memory")

// ---------------------------------------------------------------------------
// Scratch (device globals)
// ---------------------------------------------------------------------------
__device__ __half g_x2[(size_t)M_ * KD1_];    // x  fp16
__device__ __half g_y2[(size_t)M_ * KD1_];    // attn out fp16
__device__ __half g_wa2[(size_t)N3C_ * KD1_]; // snap(w_attn) fp16
__device__ __half g_wp2[(size_t)C_ * KD1_];   // snap(w_proj) fp16
__device__ __half g_qkv[(size_t)M_ * N3C_];   // qkv fp16
__device__ unsigned int g_maxbits[2];

// ---------------------------------------------------------------------------
// Prologue (exact argmin + exact division)
// ---------------------------------------------------------------------------
__global__ void zero_scales_kernel() { g_maxbits[0] = 0u; g_maxbits[1] = 0u; }

__device__ __forceinline__ void maxabs_body(const float4* __restrict__ w,
                                            int n4, int slot, int b0, int nb) {
    float m = 0.0f;
    for (int i = b0 * 256 + threadIdx.x; i < n4; i += nb * 256) {
        float4 v = w[i];
        m = fmaxf(m, fmaxf(fmaxf(fabsf(v.x), fabsf(v.y)),
                           fmaxf(fabsf(v.z), fabsf(v.w))));
    }
    #pragma unroll
    for (int o = 16; o > 0; o >>= 1)
        m = fmaxf(m, __shfl_xor_sync(0xffffffffu, m, o));
    __shared__ float sm[8];
    int lane = threadIdx.x & 31, wd = threadIdx.x >> 5;
    if (lane == 0) sm[wd] = m;
    __syncthreads();
    if (threadIdx.x < 8) {
        m = sm[threadIdx.x];
        #pragma unroll
        for (int o = 4; o > 0; o >>= 1)
            m = fmaxf(m, __shfl_xor_sync(0xffu, m, o));
        if (threadIdx.x == 0)
            atomicMax(&g_maxbits[slot], __float_as_uint(m));
    }
}

__global__ void __launch_bounds__(256) maxabs_fused(const float4* __restrict__ wa,
                                                    const float4* __restrict__ wp) {
    const int bx = blockIdx.x;
    if (bx < 384) maxabs_body(wa, (N3C_ * C_) / 4, 0, bx, 384);
    else          maxabs_body(wp, (C_ * C_) / 4, 1, bx - 384, 128);
}

// exact argmin over the 16-entry LUT (reference order, strict < tie-break)
__device__ __forceinline__ float snap1(float wn, float scale) {
    const float L1 = 1.0f,      L3 = 0.5f,      L5 = 0.333333f, L7 = 0.2f,
                L9 = 0.142857f, L11 = 0.090909f, L13 = 0.076923f;
    float bd = fabsf(wn);       // LUT[0] = 0
    float bv = 0.0f;
    #define TRY_(val) { float d_ = fabsf(wn - (val)); if (d_ < bd) { bd = d_; bv = (val); } }
    TRY_(L1)  TRY_(-L1)  TRY_(L3)  TRY_(-L3)  TRY_(L5)  TRY_(-L5)  TRY_(L7)
    TRY_(-L7) TRY_(L9)   TRY_(-L9) TRY_(L11)  TRY_(-L11) TRY_(L13) TRY_(-L13)
    #undef TRY_
    return bv * scale;
}

__device__ __forceinline__ void snap_body(const float4* __restrict__ w,
                                          __half* __restrict__ out,
                                          int n4, int slot, int b0, int nb) {
    const float scale = __uint_as_float(g_maxbits[slot]) + 1e-6f;
    for (int i = b0 * 256 + threadIdx.x; i < n4; i += nb * 256) {
        float4 wv = w[i];
        float v0 = snap1(wv.x / scale, scale);
        float v1 = snap1(wv.y / scale, scale);
        float v2 = snap1(wv.z / scale, scale);
        float v3 = snap1(wv.w / scale, scale);
        *(uint2*)(out + (size_t)i * 4) = make_uint2(packh(v0, v1), packh(v2, v3));
    }
}

__device__ __forceinline__ void cvt_body(const float4* __restrict__ a,
                                         __half* __restrict__ out,
                                         int n4, int b0, int nb) {
    for (int i = b0 * 256 + threadIdx.x; i < n4; i += nb * 256) {
        float4 v = a[i];
        *(uint2*)(out + (size_t)i * 4) = make_uint2(packh(v.x, v.y), packh(v.z, v.w));
    }
}

__global__ void __launch_bounds__(256) prep_fused(
    const float4* __restrict__ wa, const float4* __restrict__ wp,
    const float4* __restrict__ x,
    __half* __restrict__ wa2, __half* __restrict__ wp2,
    __half* __restrict__ x2)
{
    const int bx = blockIdx.x;
    if (bx < 448)       snap_body(wa, wa2, (N3C_ * C_) / 4, 0, bx, 448);
    else if (bx < 576)  snap_body(wp, wp2, (C_ * C_) / 4, 1, bx - 448, 128);
    else                cvt_body(x, x2, (M_ * C_) / 4, bx - 576, 448);
}

// ---------------------------------------------------------------------------
// fp16 single-pass mma.sync GEMM: C = A(fp16,K=1024) @ B(fp16,K=1024)^T + bias
// 128x128 tile, BK=64, 8 warps (2m x 4n), cp.async 3-stage ring, 1 barrier/iter.
// SPLIT=1: fp16 out; SPLIT=0: fp32 out.
// ---------------------------------------------------------------------------
#define GP_    144                   // smem row stride (bytes): 128 data + 16 pad
#define GT_    (128 * GP_)           // 18432 per matrix per stage
#define GSTAGE (2 * GT_)             // 36864 per stage (A,B)
#define GEMM_SMEM (3 * GSTAGE)       // 110592 (occ-2: 2x110.6KB <= 228KB)
#define GNIT_  16                    // 1024 / 64

template <int SPLIT>
__global__ void __launch_bounds__(256, 2)
gemm_mma(const __half* __restrict__ A2, const __half* __restrict__ B2,
         const float* __restrict__ bias, float* __restrict__ Cf,
         __half* __restrict__ Ch, int Nd)
{
    extern __shared__ char gsm[];
    const uint32_t sbase = smem_u32(gsm);
    const int tid  = threadIdx.x;
    const int lane = tid & 31;
    const int wid  = tid >> 5;
    const int wm   = wid >> 2;
    const int wn   = wid & 3;
    const int m0   = blockIdx.y * 128;
    const int n0   = blockIdx.x * 128;

    // loader: 2 threads/row; each thread covers 4 x 16B chunks per matrix
    const int lr  = tid >> 1;
    const int lc4 = (tid & 1) * 4;
    const __half* gA = A2 + (size_t)(m0 + lr) * KD1_;
    const __half* gB = B2 + (size_t)(n0 + lr) * KD1_;
    const uint32_t soff = (uint32_t)(lr * GP_ + lc4 * 16);

    const uint32_t aoff = (uint32_t)((wm * 64 + (lane & 15)) * GP_ + (lane >> 4) * 16);
    const uint32_t boff = (uint32_t)((wn * 32 + (lane & 7) + ((lane >> 4) & 1) * 8) * GP_
                                     + ((lane >> 3) & 1) * 16);

    float acc[4][4][4] = {};

    auto issue = [&](int it) {
        const uint32_t sb = sbase + (it % 3) * GSTAGE + soff;
        const int k0 = it * 64 + lc4 * 8;
        #pragma unroll
        for (int c = 0; c < 4; ++c)
            cp16(sb + c * 16,       gA + k0 + c * 8);
        #pragma unroll
        for (int c = 0; c < 4; ++c)
            cp16(sb + GT_ + c * 16, gB + k0 + c * 8);
        CP_COMMIT();
    };

    issue(0);
    issue(1);

    for (int it = 0; it < GNIT_; ++it) {
        if (it + 1 < GNIT_) { CP_WAIT1(); } else { CP_WAIT0(); }
        __syncthreads();
        if (it + 2 < GNIT_) issue(it + 2);   // slot (it+2)%3 last read at it-1

        const uint32_t sb = sbase + (it % 3) * GSTAGE;
        #pragma unroll
        for (int ks = 0; ks < 4; ++ks) {
            const uint32_t kso = (uint32_t)(ks * 32);
            uint32_t b0[4], b1[4], af[4][4];
            ldsm_x4(b0, sb + GT_ + boff + kso);
            ldsm_x4(b1, sb + GT_ + boff + 16 * GP_ + kso);
            #pragma unroll
            for (int mt = 0; mt < 4; ++mt)
                ldsm_x4(af[mt], sb + aoff + mt * (16 * GP_) + kso);
            #pragma unroll
            for (int mt = 0; mt < 4; ++mt) {
                mma_f16(acc[mt][0], af[mt], b0[0], b0[1]);
                mma_f16(acc[mt][1], af[mt], b0[2], b0[3]);
                mma_f16(acc[mt][2], af[mt], b1[0], b1[1]);
                mma_f16(acc[mt][3], af[mt], b1[2], b1[3]);
            }
        }
    }

    #pragma unroll
    for (int nt = 0; nt < 4; ++nt) {
        const int col = n0 + wn * 32 + nt * 8 + (lane & 3) * 2;
        const float bv0 = bias[col];
        const float bv1 = bias[col + 1];
        #pragma unroll
        for (int mt = 0; mt < 4; ++mt) {
            const int row = m0 + wm * 64 + mt * 16 + (lane >> 2);
            float v0 = acc[mt][nt][0] + bv0, v1 = acc[mt][nt][1] + bv1;
            float v2 = acc[mt][nt][2] + bv0, v3 = acc[mt][nt][3] + bv1;
            if (SPLIT) {
                *(uint32_t*)(Ch + (size_t)row * Nd + col)       = packh(v0, v1);
                *(uint32_t*)(Ch + (size_t)(row + 8) * Nd + col) = packh(v2, v3);
            } else {
                float2 o0, o1;
                o0.x = v0; o0.y = v1;
                o1.x = v2; o1.y = v3;
                *(float2*)&Cf[(size_t)row * Nd + col]       = o0;
                *(float2*)&Cf[(size_t)(row + 8) * Nd + col] = o1;
            }
        }
    }
}

// ---------------------------------------------------------------------------
// fp16 causal flash attention: single-pass S = QK^T, single-pass PV.
// 128-q tile, 8 warps x 16 rows, 64-key tiles double-buffered, occ 2.
// ---------------------------------------------------------------------------
#define SQ_    0
#define SKV0_  (128 * 144)           // 18432
#define KVB2_  (2 * 64 * 144)        // 18432 (K, V)
#define ATTN_SMEM (SKV0_ + 2 * KVB2_)    // 55296

__global__ void __launch_bounds__(256, 2)
attn_mma(const __half* __restrict__ qkv, __half* __restrict__ y2)
{
    extern __shared__ char sm[];
    const uint32_t base = smem_u32(sm);
    const int tid  = threadIdx.x;
    const int lane = tid & 31;
    const int wid  = tid >> 5;
    const int qt   = (int)gridDim.x - 1 - (int)blockIdx.x;   // long blocks first
    const int bh   = blockIdx.y;
    const int bb   = bh >> 4;
    const int h    = bh & 15;
    const int qbase = qt * 128;

    // ---- load Q tile into smem ----
    {
        const int r  = tid >> 1;
        const int c0 = (tid & 1) * 4;
        const size_t ro = ((size_t)(bb * T_ + qbase + r)) * 3072 + h * 64;
        const uint4* sq = (const uint4*)(qkv + ro) + c0;
        #pragma unroll
        for (int c = 0; c < 4; ++c)
            *(uint4*)(sm + SQ_ + r * 144 + (c0 + c) * 16) = sq[c];
    }
    __syncthreads();

    // ---- Q fragments resident in registers ----
    const uint32_t aoff = (uint32_t)((wid * 16 + (lane & 15)) * 144 + (lane >> 4) * 16);
    uint32_t qf[4][4];
    #pragma unroll
    for (int kc = 0; kc < 4; ++kc)
        ldsm_x4(qf[kc], base + SQ_ + aoff + kc * 32);

    // KV loader mapping: 64 rows x 8 uint4 per matrix, 256 threads
    const int kr  = tid >> 2;
    const int kc4 = (tid & 3) * 2;
    const int ckq = (1024 + h * 64) >> 3;
    const int cvq = (2048 + h * 64) >> 3;

    float mrow0 = -INFINITY, mrow1 = -INFINITY, lr0 = 0.0f, lr1 = 0.0f;
    float accO[8][4] = {};

    const int nkt = 2 * qt + 2;
    const int qwbase = qbase + wid * 16;
    const int r0g = qwbase + (lane >> 2);
    const float sc = 0.125f;   // 1/sqrt(64)

    uint4 stage[4];
    // load + store tile 0
    {
        const size_t ro = ((size_t)(bb * T_ + kr)) * 3072;
        const uint4* pq = (const uint4*)(qkv + ro);
        stage[0] = pq[ckq + kc4]; stage[1] = pq[ckq + kc4 + 1];
        stage[2] = pq[cvq + kc4]; stage[3] = pq[cvq + kc4 + 1];
        char* d = sm + SKV0_ + kr * 144 + kc4 * 16;
        *(uint4*)(d)            = stage[0]; *(uint4*)(d + 16)        = stage[1];
        *(uint4*)(d + 9216)     = stage[2]; *(uint4*)(d + 9216 + 16) = stage[3];
    }
    __syncthreads();

    for (int j = 0; j < nkt; ++j) {
        const int buf = j & 1;
        const int kbase = j * 64;

        if (j + 1 < nkt) {   // prefetch next tile into registers
            const size_t ro = ((size_t)(bb * T_ + (j + 1) * 64 + kr)) * 3072;
            const uint4* pq = (const uint4*)(qkv + ro);
            stage[0] = pq[ckq + kc4]; stage[1] = pq[ckq + kc4 + 1];
            stage[2] = pq[cvq + kc4]; stage[3] = pq[cvq + kc4 + 1];
        }

        if (kbase <= qwbase + 15) {   // per-warp causal skip
            const uint32_t kvb = base + SKV0_ + buf * KVB2_;

            // ---- S = Q K^T (single pass) ----
            float sa[8][4];
            #pragma unroll
            for (int nt = 0; nt < 8; ++nt)
                #pragma unroll
                for (int i = 0; i < 4; ++i) sa[nt][i] = 0.0f;

            #pragma unroll
            for (int kc = 0; kc < 4; ++kc) {
                #pragma unroll
                for (int p = 0; p < 4; ++p) {
                    const uint32_t bo = (uint32_t)((p * 16 + (lane & 7) + ((lane >> 4) & 1) * 8) * 144
                                                   + ((lane >> 3) & 1) * 16 + kc * 32);
                    uint32_t kf[4];
                    ldsm_x4(kf, kvb + bo);
                    mma_f16(sa[2 * p],     qf[kc], kf[0], kf[1]);
                    mma_f16(sa[2 * p + 1], qf[kc], kf[2], kf[3]);
                }
            }

            // ---- online softmax ----
            const bool diag = (kbase + 63 > qwbase);
            float mx0 = -INFINITY, mx1 = -INFINITY;
            #pragma unroll
            for (int nt = 0; nt < 8; ++nt) {
                const int col = kbase + nt * 8 + (lane & 3) * 2;
                float s0 = sa[nt][0] * sc, s1 = sa[nt][1] * sc;
                float s2 = sa[nt][2] * sc, s3 = sa[nt][3] * sc;
                if (diag) {
                    if (col     > r0g)     s0 = -INFINITY;
                    if (col + 1 > r0g)     s1 = -INFINITY;
                    if (col     > r0g + 8) s2 = -INFINITY;
                    if (col + 1 > r0g + 8) s3 = -INFINITY;
                }
                sa[nt][0] = s0; sa[nt][1] = s1; sa[nt][2] = s2; sa[nt][3] = s3;
                mx0 = fmaxf(mx0, fmaxf(s0, s1));
                mx1 = fmaxf(mx1, fmaxf(s2, s3));
            }
            mx0 = fmaxf(mx0, __shfl_xor_sync(0xffffffffu, mx0, 1));
            mx0 = fmaxf(mx0, __shfl_xor_sync(0xffffffffu, mx0, 2));
            mx1 = fmaxf(mx1, __shfl_xor_sync(0xffffffffu, mx1, 1));
            mx1 = fmaxf(mx1, __shfl_xor_sync(0xffffffffu, mx1, 2));

            const float mn0 = fmaxf(mrow0, mx0), mn1 = fmaxf(mrow1, mx1);
            const float f0 = __expf(mrow0 - mn0), f1 = __expf(mrow1 - mn1);
            mrow0 = mn0; mrow1 = mn1;

            float sum0 = 0.0f, sum1 = 0.0f;
            #pragma unroll
            for (int nt = 0; nt < 8; ++nt) {
                float p0 = __expf(sa[nt][0] - mn0);
                float p1 = __expf(sa[nt][1] - mn0);
                float p2 = __expf(sa[nt][2] - mn1);
                float p3 = __expf(sa[nt][3] - mn1);
                sa[nt][0] = p0; sa[nt][1] = p1; sa[nt][2] = p2; sa[nt][3] = p3;
                sum0 += p0 + p1;
                sum1 += p2 + p3;
            }
            sum0 += __shfl_xor_sync(0xffffffffu, sum0, 1);
            sum0 += __shfl_xor_sync(0xffffffffu, sum0, 2);
            sum1 += __shfl_xor_sync(0xffffffffu, sum1, 1);
            sum1 += __shfl_xor_sync(0xffffffffu, sum1, 2);
            lr0 = lr0 * f0 + sum0;
            lr1 = lr1 * f1 + sum1;
            #pragma unroll
            for (int nt = 0; nt < 8; ++nt) {
                accO[nt][0] *= f0; accO[nt][1] *= f0;
                accO[nt][2] *= f1; accO[nt][3] *= f1;
            }

            // ---- P -> A-fragments (fp16, register repack) ----
            uint32_t pf[4][4];
            #pragma unroll
            for (int kc = 0; kc < 4; ++kc) {
                #pragma unroll
                for (int half = 0; half < 2; ++half) {
                    const int nt = 2 * kc + half;
                    pf[kc][half * 2 + 0] = packh(sa[nt][0], sa[nt][1]);
                    pf[kc][half * 2 + 1] = packh(sa[nt][2], sa[nt][3]);
                }
            }

            // ---- accO += P V (single pass, ldmatrix.trans on V) ----
            const uint32_t voff = (uint32_t)((lane & 15) * 144 + (lane >> 4) * 16);
            #pragma unroll
            for (int kc = 0; kc < 4; ++kc) {
                #pragma unroll
                for (int np = 0; np < 4; ++np) {
                    uint32_t vf[4];
                    ldsm_x4_t(vf, kvb + 9216 + voff + kc * (16 * 144) + np * 32);
                    mma_f16(accO[2 * np],     pf[kc], vf[0], vf[1]);
                    mma_f16(accO[2 * np + 1], pf[kc], vf[2], vf[3]);
                }
            }
        }

        if (j + 1 < nkt) {   // store prefetched tile into the other buffer
            char* d = sm + SKV0_ + (1 - buf) * KVB2_ + kr * 144 + kc4 * 16;
            *(uint4*)(d)            = stage[0]; *(uint4*)(d + 16)        = stage[1];
            *(uint4*)(d + 9216)     = stage[2]; *(uint4*)(d + 9216 + 16) = stage[3];
        }
        __syncthreads();
    }

    // ---- epilogue: normalize, write fp16 y (stride 1024) ----
    const float inv0 = 1.0f / lr0, inv1 = 1.0f / lr1;
    const size_t row0 = (size_t)(bb * T_ + qwbase + (lane >> 2));
    const int colb = h * 64 + (lane & 3) * 2;
    #pragma unroll
    for (int nt = 0; nt < 8; ++nt) {
        const int col = colb + nt * 8;
        *(uint32_t*)(y2 + row0 * KD1_ + col)       = packh(accO[nt][0] * inv0, accO[nt][1] * inv0);
        *(uint32_t*)(y2 + (row0 + 8) * KD1_ + col) = packh(accO[nt][2] * inv1, accO[nt][3] * inv1);
    }
}

// ---------------------------------------------------------------------------
// Launch
// ---------------------------------------------------------------------------
extern "C" void kernel_launch(void* const* d_in, const int* in_sizes, int n_in,
                              void* d_out, int out_size)
{
    (void)in_sizes; (void)n_in; (void)out_size;
    const float* x      = (const float*)d_in[0];
    const float* w_attn = (const float*)d_in[1];
    const float* b_attn = (const float*)d_in[2];
    const float* w_proj = (const float*)d_in[3];
    const float* b_proj = (const float*)d_in[4];
    float* out = (float*)d_out;

    __half *x2, *y2, *wa2, *wp2, *qkv;
    cudaGetSymbolAddress((void**)&x2,  g_x2);
    cudaGetSymbolAddress((void**)&y2,  g_y2);
    cudaGetSymbolAddress((void**)&wa2, g_wa2);
    cudaGetSymbolAddress((void**)&wp2, g_wp2);
    cudaGetSymbolAddress((void**)&qkv, g_qkv);

    cudaFuncSetAttribute(attn_mma, cudaFuncAttributeMaxDynamicSharedMemorySize,
                         ATTN_SMEM);
    cudaFuncSetAttribute(gemm_mma<1>, cudaFuncAttributeMaxDynamicSharedMemorySize,
                         GEMM_SMEM);
    cudaFuncSetAttribute(gemm_mma<0>, cudaFuncAttributeMaxDynamicSharedMemorySize,
                         GEMM_SMEM);

    // 1) prologue: scales, snap -> fp16, x -> fp16
    zero_scales_kernel<<<1, 1>>>();
    maxabs_fused<<<512, 256>>>((const float4*)w_attn, (const float4*)w_proj);
    prep_fused<<<1024, 256>>>((const float4*)w_attn, (const float4*)w_proj,
                              (const float4*)x, wa2, wp2, x2);

    // 2) qkv = x @ snap(w_attn)^T + b_attn  (single-pass fp16, BK=64)
    gemm_mma<1><<<dim3(N3C_ / 128, M_ / 128), 256, GEMM_SMEM>>>(
        x2, wa2, b_attn, nullptr, qkv, N3C_);

    // 3) causal flash attention -> y2 (fp16)
    attn_mma<<<dim3(T_ / 128, B_ * H_), 256, ATTN_SMEM>>>(qkv, y2);

    // 4) out = y @ snap(w_proj)^T + b_proj  (fp32 out)
    gemm_mma<0><<<dim3(C_ / 128, M_ / 128), 256, GEMM_SMEM>>>(
        y2, wp2, b_proj, out, nullptr, C_);
}

// round 16
// speedup vs baseline: 1.0453x; 1.0453x over previous
#include <cuda_runtime.h>
#include <cuda_fp16.h>
#include <math.h>
#include <stdint.h>

// Problem constants
#define B_   2
#define T_   2048
#define C_   1024
#define H_   16
#define M_   (B_ * T_)      // 4096
#define N3C_ (3 * C_)       // 3072
#define KD1_ 1024           // single-fp16 K width

// ---------------------------------------------------------------------------
// Helpers
// ---------------------------------------------------------------------------
__device__ __forceinline__ uint32_t smem_u32(const void* p) {
    uint32_t a;
    asm("{ .reg .u64 t; cvta.to.shared.u64 t, %1; cvt.u32.u64 %0, t; }"
        : "=r"(a) : "l"(p));
    return a;
}

__device__ __forceinline__ void ldsm_x4(uint32_t (&r)[4], uint32_t addr) {
    asm volatile("ldmatrix.sync.aligned.m8n8.x4.shared.b16 {%0,%1,%2,%3}, [%4];"
                 : "=r"(r[0]), "=r"(r[1]), "=r"(r[2]), "=r"(r[3]) : "r"(addr));
}

__device__ __forceinline__ void ldsm_x4_t(uint32_t (&r)[4], uint32_t addr) {
    asm volatile("ldmatrix.sync.aligned.m8n8.x4.trans.shared.b16 {%0,%1,%2,%3}, [%4];"
                 : "=r"(r[0]), "=r"(r[1]), "=r"(r[2]), "=r"(r[3]) : "r"(addr));
}

__device__ __forceinline__ void mma_f16(float (&c)[4], const uint32_t (&a)[4],
                                        uint32_t b0, uint32_t b1) {
    asm volatile(
        "mma.sync.aligned.m16n8k16.row.col.f32.f16.f16.f32 "
        "{%0,%1,%2,%3}, {%4,%5,%6,%7}, {%8,%9}, {%0,%1,%2,%3};"
        : "+f"(c[0]), "+f"(c[1]), "+f"(c[2]), "+f"(c[3])
        : "r"(a[0]), "r"(a[1]), "r"(a[2]), "r"(a[3]), "r"(b0), "r"(b1));
}

// pack two f32 -> f16x2, first arg in lower half
__device__ __forceinline__ uint32_t packh(float lo, float hi) {
    uint32_t u;
    asm("cvt.rn.f16x2.f32 %0, %1, %2;" : "=r"(u) : "f"(hi), "f"(lo));
    return u;
}

__device__ __forceinline__ void cp16(uint32_t dst, const void* src) {
    asm volatile("cp.async.cg.shared.global [%0], [%1], 16;"
                 :: "r"(dst), "l"(src) : "memory");
}
#define CP_COMMIT() asm volatile("cp.async.commit_group;" ::: "memory")
#define CP_WAIT1()  asm volatile("cp.async.wait_group 1;" ::: "memory")
#define CP_WAIT0()  asm volatile("cp.async.wait_group 0;" ::: "memory")

// ---------------------------------------------------------------------------
// Scratch (device globals)
// ---------------------------------------------------------------------------
__device__ __half g_x2[(size_t)M_ * KD1_];    // x  fp16
__device__ __half g_y2[(size_t)M_ * KD1_];    // attn out fp16
__device__ __half g_wa2[(size_t)N3C_ * KD1_]; // snap(w_attn) fp16
__device__ __half g_wp2[(size_t)C_ * KD1_];   // snap(w_proj) fp16
__device__ __half g_qkv[(size_t)M_ * N3C_];   // qkv fp16
__device__ unsigned int g_maxbits[2];

// ---------------------------------------------------------------------------
// Prologue (exact argmin + exact division)
// ---------------------------------------------------------------------------
__global__ void zero_scales_kernel() { g_maxbits[0] = 0u; g_maxbits[1] = 0u; }

__device__ __forceinline__ void maxabs_body(const float4* __restrict__ w,
                                            int n4, int slot, int b0, int nb) {
    float m = 0.0f;
    for (int i = b0 * 256 + threadIdx.x; i < n4; i += nb * 256) {
        float4 v = w[i];
        m = fmaxf(m, fmaxf(fmaxf(fabsf(v.x), fabsf(v.y)),
                           fmaxf(fabsf(v.z), fabsf(v.w))));
    }
    #pragma unroll
    for (int o = 16; o > 0; o >>= 1)
        m = fmaxf(m, __shfl_xor_sync(0xffffffffu, m, o));
    __shared__ float sm[8];
    int lane = threadIdx.x & 31, wd = threadIdx.x >> 5;
    if (lane == 0) sm[wd] = m;
    __syncthreads();
    if (threadIdx.x < 8) {
        m = sm[threadIdx.x];
        #pragma unroll
        for (int o = 4; o > 0; o >>= 1)
            m = fmaxf(m, __shfl_xor_sync(0xffu, m, o));
        if (threadIdx.x == 0)
            atomicMax(&g_maxbits[slot], __float_as_uint(m));
    }
}

__global__ void __launch_bounds__(256) maxabs_fused(const float4* __restrict__ wa,
                                                    const float4* __restrict__ wp) {
    const int bx = blockIdx.x;
    if (bx < 384) maxabs_body(wa, (N3C_ * C_) / 4, 0, bx, 384);
    else          maxabs_body(wp, (C_ * C_) / 4, 1, bx - 384, 128);
}

// exact argmin over the 16-entry LUT (reference order, strict < tie-break)
__device__ __forceinline__ float snap1(float wn, float scale) {
    const float L1 = 1.0f,      L3 = 0.5f,      L5 = 0.333333f, L7 = 0.2f,
                L9 = 0.142857f, L11 = 0.090909f, L13 = 0.076923f;
    float bd = fabsf(wn);       // LUT[0] = 0
    float bv = 0.0f;
    #define TRY_(val) { float d_ = fabsf(wn - (val)); if (d_ < bd) { bd = d_; bv = (val); } }
    TRY_(L1)  TRY_(-L1)  TRY_(L3)  TRY_(-L3)  TRY_(L5)  TRY_(-L5)  TRY_(L7)
    TRY_(-L7) TRY_(L9)   TRY_(-L9) TRY_(L11)  TRY_(-L11) TRY_(L13) TRY_(-L13)
    #undef TRY_
    return bv * scale;
}

__device__ __forceinline__ void snap_body(const float4* __restrict__ w,
                                          __half* __restrict__ out,
                                          int n4, int slot, int b0, int nb) {
    const float scale = __uint_as_float(g_maxbits[slot]) + 1e-6f;
    for (int i = b0 * 256 + threadIdx.x; i < n4; i += nb * 256) {
        float4 wv = w[i];
        float v0 = snap1(wv.x / scale, scale);
        float v1 = snap1(wv.y / scale, scale);
        float v2 = snap1(wv.z / scale, scale);
        float v3 = snap1(wv.w / scale, scale);
        *(uint2*)(out + (size_t)i * 4) = make_uint2(packh(v0, v1), packh(v2, v3));
    }
}

__device__ __forceinline__ void cvt_body(const float4* __restrict__ a,
                                         __half* __restrict__ out,
                                         int n4, int b0, int nb) {
    for (int i = b0 * 256 + threadIdx.x; i < n4; i += nb * 256) {
        float4 v = a[i];
        *(uint2*)(out + (size_t)i * 4) = make_uint2(packh(v.x, v.y), packh(v.z, v.w));
    }
}

__global__ void __launch_bounds__(256) prep_fused(
    const float4* __restrict__ wa, const float4* __restrict__ wp,
    const float4* __restrict__ x,
    __half* __restrict__ wa2, __half* __restrict__ wp2,
    __half* __restrict__ x2)
{
    const int bx = blockIdx.x;
    if (bx < 448)       snap_body(wa, wa2, (N3C_ * C_) / 4, 0, bx, 448);
    else if (bx < 576)  snap_body(wp, wp2, (C_ * C_) / 4, 1, bx - 448, 128);
    else                cvt_body(x, x2, (M_ * C_) / 4, bx - 576, 448);
}

// ---------------------------------------------------------------------------
// fp16 single-pass mma.sync GEMM: C = A(fp16,K=1024) @ B(fp16,K=1024)^T + bias
// 64x128 tile, BK=32, 128 threads (4 warps, 1m x 4n), cp.async 3-stage ring,
// occ 4 CTAs/SM. SPLIT=1: fp16 out; SPLIT=0: fp32 out.
// ---------------------------------------------------------------------------
#define GP_    80                    // smem row stride (bytes)
#define GTA_   (64 * GP_)            // 5120  A tile per stage
#define GTB_   (128 * GP_)           // 10240 B tile per stage
#define GSTAGE (GTA_ + GTB_)         // 15360 per stage
#define GEMM_SMEM (3 * GSTAGE)       // 46080 (occ-4: 4x46KB <= 228KB)
#define GNIT_  32                    // 1024 / 32

template <int SPLIT>
__global__ void __launch_bounds__(128, 4)
gemm_mma(const __half* __restrict__ A2, const __half* __restrict__ B2,
         const float* __restrict__ bias, float* __restrict__ Cf,
         __half* __restrict__ Ch, int Nd)
{
    extern __shared__ char gsm[];
    const uint32_t sbase = smem_u32(gsm);
    const int tid  = threadIdx.x;
    const int lane = tid & 31;
    const int wn   = tid >> 5;            // 4 warps, all share A rows
    const int m0   = blockIdx.y * 64;
    const int n0   = blockIdx.x * 128;

    // loader: A = 64 rows (2 thr/row, 2 chunks each); B = 128 rows (2 rows/thr)
    const int lr  = tid >> 1;             // 0..63
    const int lc2 = (tid & 1) * 2;        // chunk 0-1 or 2-3
    const __half* gA  = A2 + (size_t)(m0 + lr) * KD1_;
    const __half* gB0 = B2 + (size_t)(n0 + lr) * KD1_;
    const __half* gB1 = B2 + (size_t)(n0 + lr + 64) * KD1_;
    const uint32_t sAo = (uint32_t)(lr * GP_ + lc2 * 16);
    const uint32_t sBo0 = (uint32_t)(GTA_ + lr * GP_ + lc2 * 16);
    const uint32_t sBo1 = sBo0 + 64 * GP_;

    const uint32_t aoff = (uint32_t)((lane & 15) * GP_ + (lane >> 4) * 16);
    const uint32_t boff = (uint32_t)(GTA_ + (wn * 32 + (lane & 7) + ((lane >> 4) & 1) * 8) * GP_
                                     + ((lane >> 3) & 1) * 16);

    float acc[4][4][4] = {};

    auto issue = [&](int it) {
        const uint32_t sb = sbase + (it % 3) * GSTAGE;
        const int k0 = it * 32 + lc2 * 8;
        cp16(sb + sAo,        gA + k0);
        cp16(sb + sAo + 16,   gA + k0 + 8);
        cp16(sb + sBo0,       gB0 + k0);
        cp16(sb + sBo0 + 16,  gB0 + k0 + 8);
        cp16(sb + sBo1,       gB1 + k0);
        cp16(sb + sBo1 + 16,  gB1 + k0 + 8);
        CP_COMMIT();
    };

    issue(0);
    issue(1);

    for (int it = 0; it < GNIT_; ++it) {
        if (it + 1 < GNIT_) { CP_WAIT1(); } else { CP_WAIT0(); }
        __syncthreads();
        if (it + 2 < GNIT_) issue(it + 2);   // slot (it+2)%3 last read at it-1

        const uint32_t sb = sbase + (it % 3) * GSTAGE;
        #pragma unroll
        for (int ks = 0; ks < 2; ++ks) {
            const uint32_t kso = (uint32_t)(ks * 32);
            uint32_t b0[4], b1[4], af[4][4];
            ldsm_x4(b0, sb + boff + kso);
            ldsm_x4(b1, sb + boff + 16 * GP_ + kso);
            #pragma unroll
            for (int mt = 0; mt < 4; ++mt)
                ldsm_x4(af[mt], sb + aoff + mt * (16 * GP_) + kso);
            #pragma unroll
            for (int mt = 0; mt < 4; ++mt) {
                mma_f16(acc[mt][0], af[mt], b0[0], b0[1]);
                mma_f16(acc[mt][1], af[mt], b0[2], b0[3]);
                mma_f16(acc[mt][2], af[mt], b1[0], b1[1]);
                mma_f16(acc[mt][3], af[mt], b1[2], b1[3]);
            }
        }
    }

    #pragma unroll
    for (int nt = 0; nt < 4; ++nt) {
        const int col = n0 + wn * 32 + nt * 8 + (lane & 3) * 2;
        const float bv0 = bias[col];
        const float bv1 = bias[col + 1];
        #pragma unroll
        for (int mt = 0; mt < 4; ++mt) {
            const int row = m0 + mt * 16 + (lane >> 2);
            float v0 = acc[mt][nt][0] + bv0, v1 = acc[mt][nt][1] + bv1;
            float v2 = acc[mt][nt][2] + bv0, v3 = acc[mt][nt][3] + bv1;
            if (SPLIT) {
                *(uint32_t*)(Ch + (size_t)row * Nd + col)       = packh(v0, v1);
                *(uint32_t*)(Ch + (size_t)(row + 8) * Nd + col) = packh(v2, v3);
            } else {
                float2 o0, o1;
                o0.x = v0; o0.y = v1;
                o1.x = v2; o1.y = v3;
                *(float2*)&Cf[(size_t)row * Nd + col]       = o0;
                *(float2*)&Cf[(size_t)(row + 8) * Nd + col] = o1;
            }
        }
    }
}

// ---------------------------------------------------------------------------
// fp16 causal flash attention: single-pass S = QK^T, single-pass PV.
// 128-q tile, 8 warps x 16 rows, 64-key tiles double-buffered, occ 2.
// (R14-exact)
// ---------------------------------------------------------------------------
#define SQ_    0
#define SKV0_  (128 * 144)           // 18432
#define KVB2_  (2 * 64 * 144)        // 18432 (K, V)
#define ATTN_SMEM (SKV0_ + 2 * KVB2_)    // 55296

__global__ void __launch_bounds__(256, 2)
attn_mma(const __half* __restrict__ qkv, __half* __restrict__ y2)
{
    extern __shared__ char sm[];
    const uint32_t base = smem_u32(sm);
    const int tid  = threadIdx.x;
    const int lane = tid & 31;
    const int wid  = tid >> 5;
    const int qt   = (int)gridDim.x - 1 - (int)blockIdx.x;   // long blocks first
    const int bh   = blockIdx.y;
    const int bb   = bh >> 4;
    const int h    = bh & 15;
    const int qbase = qt * 128;

    // ---- load Q tile into smem ----
    {
        const int r  = tid >> 1;
        const int c0 = (tid & 1) * 4;
        const size_t ro = ((size_t)(bb * T_ + qbase + r)) * 3072 + h * 64;
        const uint4* sq = (const uint4*)(qkv + ro) + c0;
        #pragma unroll
        for (int c = 0; c < 4; ++c)
            *(uint4*)(sm + SQ_ + r * 144 + (c0 + c) * 16) = sq[c];
    }
    __syncthreads();

    // ---- Q fragments resident in registers ----
    const uint32_t aoff = (uint32_t)((wid * 16 + (lane & 15)) * 144 + (lane >> 4) * 16);
    uint32_t qf[4][4];
    #pragma unroll
    for (int kc = 0; kc < 4; ++kc)
        ldsm_x4(qf[kc], base + SQ_ + aoff + kc * 32);

    // KV loader mapping: 64 rows x 8 uint4 per matrix, 256 threads
    const int kr  = tid >> 2;
    const int kc4 = (tid & 3) * 2;
    const int ckq = (1024 + h * 64) >> 3;
    const int cvq = (2048 + h * 64) >> 3;

    float mrow0 = -INFINITY, mrow1 = -INFINITY, lr0 = 0.0f, lr1 = 0.0f;
    float accO[8][4] = {};

    const int nkt = 2 * qt + 2;
    const int qwbase = qbase + wid * 16;
    const int r0g = qwbase + (lane >> 2);
    const float sc = 0.125f;   // 1/sqrt(64)

    uint4 stage[4];
    // load + store tile 0
    {
        const size_t ro = ((size_t)(bb * T_ + kr)) * 3072;
        const uint4* pq = (const uint4*)(qkv + ro);
        stage[0] = pq[ckq + kc4]; stage[1] = pq[ckq + kc4 + 1];
        stage[2] = pq[cvq + kc4]; stage[3] = pq[cvq + kc4 + 1];
        char* d = sm + SKV0_ + kr * 144 + kc4 * 16;
        *(uint4*)(d)            = stage[0]; *(uint4*)(d + 16)        = stage[1];
        *(uint4*)(d + 9216)     = stage[2]; *(uint4*)(d + 9216 + 16) = stage[3];
    }
    __syncthreads();

    for (int j = 0; j < nkt; ++j) {
        const int buf = j & 1;
        const int kbase = j * 64;

        if (j + 1 < nkt) {   // prefetch next tile into registers
            const size_t ro = ((size_t)(bb * T_ + (j + 1) * 64 + kr)) * 3072;
            const uint4* pq = (const uint4*)(qkv + ro);
            stage[0] = pq[ckq + kc4]; stage[1] = pq[ckq + kc4 + 1];
            stage[2] = pq[cvq + kc4]; stage[3] = pq[cvq + kc4 + 1];
        }

        if (kbase <= qwbase + 15) {   // per-warp causal skip
            const uint32_t kvb = base + SKV0_ + buf * KVB2_;

            // ---- S = Q K^T (single pass) ----
            float sa[8][4];
            #pragma unroll
            for (int nt = 0; nt < 8; ++nt)
                #pragma unroll
                for (int i = 0; i < 4; ++i) sa[nt][i] = 0.0f;

            #pragma unroll
            for (int kc = 0; kc < 4; ++kc) {
                #pragma unroll
                for (int p = 0; p < 4; ++p) {
                    const uint32_t bo = (uint32_t)((p * 16 + (lane & 7) + ((lane >> 4) & 1) * 8) * 144
                                                   + ((lane >> 3) & 1) * 16 + kc * 32);
                    uint32_t kf[4];
                    ldsm_x4(kf, kvb + bo);
                    mma_f16(sa[2 * p],     qf[kc], kf[0], kf[1]);
                    mma_f16(sa[2 * p + 1], qf[kc], kf[2], kf[3]);
                }
            }

            // ---- online softmax ----
            const bool diag = (kbase + 63 > qwbase);
            float mx0 = -INFINITY, mx1 = -INFINITY;
            #pragma unroll
            for (int nt = 0; nt < 8; ++nt) {
                const int col = kbase + nt * 8 + (lane & 3) * 2;
                float s0 = sa[nt][0] * sc, s1 = sa[nt][1] * sc;
                float s2 = sa[nt][2] * sc, s3 = sa[nt][3] * sc;
                if (diag) {
                    if (col     > r0g)     s0 = -INFINITY;
                    if (col + 1 > r0g)     s1 = -INFINITY;
                    if (col     > r0g + 8) s2 = -INFINITY;
                    if (col + 1 > r0g + 8) s3 = -INFINITY;
                }
                sa[nt][0] = s0; sa[nt][1] = s1; sa[nt][2] = s2; sa[nt][3] = s3;
                mx0 = fmaxf(mx0, fmaxf(s0, s1));
                mx1 = fmaxf(mx1, fmaxf(s2, s3));
            }
            mx0 = fmaxf(mx0, __shfl_xor_sync(0xffffffffu, mx0, 1));
            mx0 = fmaxf(mx0, __shfl_xor_sync(0xffffffffu, mx0, 2));
            mx1 = fmaxf(mx1, __shfl_xor_sync(0xffffffffu, mx1, 1));
            mx1 = fmaxf(mx1, __shfl_xor_sync(0xffffffffu, mx1, 2));

            const float mn0 = fmaxf(mrow0, mx0), mn1 = fmaxf(mrow1, mx1);
            const float f0 = __expf(mrow0 - mn0), f1 = __expf(mrow1 - mn1);
            mrow0 = mn0; mrow1 = mn1;

            float sum0 = 0.0f, sum1 = 0.0f;
            #pragma unroll
            for (int nt = 0; nt < 8; ++nt) {
                float p0 = __expf(sa[nt][0] - mn0);
                float p1 = __expf(sa[nt][1] - mn0);
                float p2 = __expf(sa[nt][2] - mn1);
                float p3 = __expf(sa[nt][3] - mn1);
                sa[nt][0] = p0; sa[nt][1] = p1; sa[nt][2] = p2; sa[nt][3] = p3;
                sum0 += p0 + p1;
                sum1 += p2 + p3;
            }
            sum0 += __shfl_xor_sync(0xffffffffu, sum0, 1);
            sum0 += __shfl_xor_sync(0xffffffffu, sum0, 2);
            sum1 += __shfl_xor_sync(0xffffffffu, sum1, 1);
            sum1 += __shfl_xor_sync(0xffffffffu, sum1, 2);
            lr0 = lr0 * f0 + sum0;
            lr1 = lr1 * f1 + sum1;
            #pragma unroll
            for (int nt = 0; nt < 8; ++nt) {
                accO[nt][0] *= f0; accO[nt][1] *= f0;
                accO[nt][2] *= f1; accO[nt][3] *= f1;
            }

            // ---- P -> A-fragments (fp16, register repack) ----
            uint32_t pf[4][4];
            #pragma unroll
            for (int kc = 0; kc < 4; ++kc) {
                #pragma unroll
                for (int half = 0; half < 2; ++half) {
                    const int nt = 2 * kc + half;
                    pf[kc][half * 2 + 0] = packh(sa[nt][0], sa[nt][1]);
                    pf[kc][half * 2 + 1] = packh(sa[nt][2], sa[nt][3]);
                }
            }

            // ---- accO += P V (single pass, ldmatrix.trans on V) ----
            const uint32_t voff = (uint32_t)((lane & 15) * 144 + (lane >> 4) * 16);
            #pragma unroll
            for (int kc = 0; kc < 4; ++kc) {
                #pragma unroll
                for (int np = 0; np < 4; ++np) {
                    uint32_t vf[4];
                    ldsm_x4_t(vf, kvb + 9216 + voff + kc * (16 * 144) + np * 32);
                    mma_f16(accO[2 * np],     pf[kc], vf[0], vf[1]);
                    mma_f16(accO[2 * np + 1], pf[kc], vf[2], vf[3]);
                }
            }
        }

        if (j + 1 < nkt) {   // store prefetched tile into the other buffer
            char* d = sm + SKV0_ + (1 - buf) * KVB2_ + kr * 144 + kc4 * 16;
            *(uint4*)(d)            = stage[0]; *(uint4*)(d + 16)        = stage[1];
            *(uint4*)(d + 9216)     = stage[2]; *(uint4*)(d + 9216 + 16) = stage[3];
        }
        __syncthreads();
    }

    // ---- epilogue: normalize, write fp16 y (stride 1024) ----
    const float inv0 = 1.0f / lr0, inv1 = 1.0f / lr1;
    const size_t row0 = (size_t)(bb * T_ + qwbase + (lane >> 2));
    const int colb = h * 64 + (lane & 3) * 2;
    #pragma unroll
    for (int nt = 0; nt < 8; ++nt) {
        const int col = colb + nt * 8;
        *(uint32_t*)(y2 + row0 * KD1_ + col)       = packh(accO[nt][0] * inv0, accO[nt][1] * inv0);
        *(uint32_t*)(y2 + (row0 + 8) * KD1_ + col) = packh(accO[nt][2] * inv1, accO[nt][3] * inv1);
    }
}

// ---------------------------------------------------------------------------
// Launch
// ---------------------------------------------------------------------------
extern "C" void kernel_launch(void* const* d_in, const int* in_sizes, int n_in,
                              void* d_out, int out_size)
{
    (void)in_sizes; (void)n_in; (void)out_size;
    const float* x      = (const float*)d_in[0];
    const float* w_attn = (const float*)d_in[1];
    const float* b_attn = (const float*)d_in[2];
    const float* w_proj = (const float*)d_in[3];
    const float* b_proj = (const float*)d_in[4];
    float* out = (float*)d_out;

    __half *x2, *y2, *wa2, *wp2, *qkv;
    cudaGetSymbolAddress((void**)&x2,  g_x2);
    cudaGetSymbolAddress((void**)&y2,  g_y2);
    cudaGetSymbolAddress((void**)&wa2, g_wa2);
    cudaGetSymbolAddress((void**)&wp2, g_wp2);
    cudaGetSymbolAddress((void**)&qkv, g_qkv);

    cudaFuncSetAttribute(attn_mma, cudaFuncAttributeMaxDynamicSharedMemorySize,
                         ATTN_SMEM);
    cudaFuncSetAttribute(gemm_mma<1>, cudaFuncAttributeMaxDynamicSharedMemorySize,
                         GEMM_SMEM);
    cudaFuncSetAttribute(gemm_mma<0>, cudaFuncAttributeMaxDynamicSharedMemorySize,
                         GEMM_SMEM);

    // 1) prologue: scales, snap -> fp16, x -> fp16
    zero_scales_kernel<<<1, 1>>>();
    maxabs_fused<<<512, 256>>>((const float4*)w_attn, (const float4*)w_proj);
    prep_fused<<<1024, 256>>>((const float4*)w_attn, (const float4*)w_proj,
                              (const float4*)x, wa2, wp2, x2);

    // 2) qkv = x @ snap(w_attn)^T + b_attn  (single-pass fp16, 64x128 tiles)
    gemm_mma<1><<<dim3(N3C_ / 128, M_ / 64), 128, GEMM_SMEM>>>(
        x2, wa2, b_attn, nullptr, qkv, N3C_);

    // 3) causal flash attention -> y2 (fp16)
    attn_mma<<<dim3(T_ / 128, B_ * H_), 256, ATTN_SMEM>>>(qkv, y2);

    // 4) out = y @ snap(w_proj)^T + b_proj  (fp32 out)
    gemm_mma<0><<<dim3(C_ / 128, M_ / 64), 128, GEMM_SMEM>>>(
        y2, wp2, b_proj, out, nullptr, C_);
}